// round 3
// baseline (speedup 1.0000x reference)
#include <cuda_runtime.h>
#include <cuda_bf16.h>
#include <cstdint>

#define NN        2048
#define GRID      152
#define MEM       32
#define HID       256
#define W1S_STRIDE 260   // words; row stride 1040B (16B multiple, bank-conflict-free gathers)

// dynamic smem byte offsets
#define OFF_W1(b)   ((b) * 33280)            // 2 x 33280
#define OFF_XRAW(b) (66560 + (b) * 16384)    // 2 x 16384
#define OFF_XF      99328                    // 16384
#define OFF_PART    115712                   // 16 KB (16 warps x 128 rows x 2)
#define SMEM_TOTAL  132096

__device__ __forceinline__ float sigmoidf_fast(float x) {
    return __fdividef(1.0f, 1.0f + __expf(-x));
}

__device__ __forceinline__ void mma_bf16(float c[4],
                                         uint32_t a0, uint32_t a1, uint32_t a2, uint32_t a3,
                                         uint32_t b0, uint32_t b1) {
    asm volatile(
        "mma.sync.aligned.m16n8k16.row.col.f32.bf16.bf16.f32 "
        "{%0,%1,%2,%3}, {%4,%5,%6,%7}, {%8,%9}, {%0,%1,%2,%3};"
        : "+f"(c[0]), "+f"(c[1]), "+f"(c[2]), "+f"(c[3])
        : "r"(a0), "r"(a1), "r"(a2), "r"(a3), "r"(b0), "r"(b1));
}

__device__ __forceinline__ void split_pack(float x, float y, uint32_t& hi, uint32_t& lo) {
    __nv_bfloat16 hx = __float2bfloat16(x);
    __nv_bfloat16 hy = __float2bfloat16(y);
    float rx = x - __bfloat162float(hx);
    float ry = y - __bfloat162float(hy);
    __nv_bfloat16 lx = __float2bfloat16(rx);
    __nv_bfloat16 ly = __float2bfloat16(ry);
    hi = ((uint32_t)__bfloat16_as_ushort(hy) << 16) | (uint32_t)__bfloat16_as_ushort(hx);
    lo = ((uint32_t)__bfloat16_as_ushort(ly) << 16) | (uint32_t)__bfloat16_as_ushort(lx);
}

__device__ __forceinline__ void cp16(uint32_t dst, const void* src) {
    asm volatile("cp.async.cg.shared.global [%0], [%1], 16;" :: "r"(dst), "l"(src));
}
__device__ __forceinline__ void cp_commit() { asm volatile("cp.async.commit_group;"); }
__device__ __forceinline__ void cp_wait0()  { asm volatile("cp.async.wait_group 0;"); }

__device__ __forceinline__ void prefetch_neuron(uint32_t sbase, int buf, int n, int tid,
                                                const float* __restrict__ state,
                                                const float* __restrict__ w1) {
    const float* Xg  = state + (size_t)n * MEM;     // row stride 65536 floats
    const float* W1g = w1 + (size_t)n * (MEM * HID);
    const uint32_t xd = sbase + OFF_XRAW(buf);
    #pragma unroll
    for (int j = 0; j < 2; j++) {
        const int c   = tid + 512 * j;
        const int row = c >> 3;
        const int s   = c & 7;
        cp16(xd + c * 16, Xg + (size_t)row * (NN * MEM) + 4 * s);
    }
    const uint32_t wd = sbase + OFF_W1(buf);
    #pragma unroll
    for (int j = 0; j < 4; j++) {
        const int c  = tid + 512 * j;
        const int k  = c >> 6;
        const int c4 = c & 63;
        cp16(wd + (k * W1S_STRIDE + 4 * c4) * 4, W1g + k * HID + 4 * c4);
    }
    cp_commit();
}

__global__ __launch_bounds__(512, 1)
void nlm_kernel(const float* __restrict__ state,   // (128, 2048, 32)
                const float* __restrict__ w1,      // (2048, 32, 256)
                const float* __restrict__ b1,      // (2048, 256)
                const float* __restrict__ w2,      // (2048, 128, 2)
                const float* __restrict__ b2,      // (2048, 2)
                const float* __restrict__ Tg,      // (1,)
                float* __restrict__ out)           // (128, 2048)
{
    extern __shared__ char smem[];
    const uint32_t sbase = (uint32_t)__cvta_generic_to_shared(smem);
    uint2* XF      = (uint2*)(smem + OFF_XF);
    float* part    = (float*)(smem + OFF_PART);

    const int bid  = blockIdx.x;
    const int tid  = threadIdx.x;
    const int w    = tid >> 5;      // 0..15: owns GLU columns [8w, 8w+8)
    const int lane = tid & 31;
    const int q    = lane & 3;
    const int lr   = lane >> 2;

    const float Tval = Tg[0];
    const int cnt = (NN - 1 - bid) / GRID + 1;   // 13 or 14 neurons

    // prologue: prefetch first neuron
    prefetch_neuron(sbase, 0, bid, tid, state, w1);

    for (int it = 0; it < cnt; it++) {
        const int n   = bid + GRID * it;
        const int buf = it & 1;

        cp_wait0();
        __syncthreads();

        // prefetch next neuron into the other buffer (overlaps everything below)
        if (it + 1 < cnt)
            prefetch_neuron(sbase, buf ^ 1, bid + GRID * (it + 1), tid, state, w1);

        // per-warp bias / W2 registers (issued early, consumed in mainloop)
        const int h0 = w * 8 + 2 * q;
        const float2 ba  = *reinterpret_cast<const float2*>(&b1[n * 256 + h0]);
        const float2 bb  = *reinterpret_cast<const float2*>(&b1[n * 256 + 128 + h0]);
        const float4 w2f = *reinterpret_cast<const float4*>(&w2[n * 256 + h0 * 2]);
        float2 b2v = make_float2(0.f, 0.f);
        if (tid < 128) b2v = *reinterpret_cast<const float2*>(&b2[n * 2]);

        // ---- convert X raw -> bf16 hi/lo fragment layout ----
        const float4* xr4 = (const float4*)(smem + OFF_XRAW(buf));
        #pragma unroll
        for (int j = 0; j < 2; j++) {
            const int t    = tid + 512 * j;
            const int s    = t & 7;
            const int brow = t >> 3;
            const float4 v = xr4[t];
            const int p0   = 2 * s;
            const int q0   = p0 & 3;
            const int reg2 = (p0 >> 2) & 1;
            const int ks   = p0 >> 3;
            const int flr  = brow & 7;
            const int reg  = ((brow >> 3) & 1) + 2 * reg2;
            const int m    = brow >> 4;
            const int idx  = ((m * 2 + ks) * 4 + reg) * 32 + flr * 4 + q0;
            uint4 hl;
            split_pack(v.x, v.y, hl.x, hl.y);
            split_pack(v.z, v.w, hl.z, hl.w);
            *reinterpret_cast<uint4*>(&XF[idx]) = hl;
        }

        // ---- build W1 fragments (conflict-free smem gathers) ----
        const float* W1s = (const float*)(smem + OFF_W1(buf));
        uint32_t BAhi[2][2], BAlo[2][2], BBhi[2][2], BBlo[2][2];
        const int colA = w * 8 + lr;
        const int colB = colA + 128;
        #pragma unroll
        for (int ks = 0; ks < 2; ks++) {
            #pragma unroll
            for (int r = 0; r < 2; r++) {
                const int k = ks * 16 + r * 8 + 2 * q;
                float a0 = W1s[k * W1S_STRIDE + colA];
                float a1 = W1s[(k + 1) * W1S_STRIDE + colA];
                split_pack(a0, a1, BAhi[ks][r], BAlo[ks][r]);
                float c0 = W1s[k * W1S_STRIDE + colB];
                float c1 = W1s[(k + 1) * W1S_STRIDE + colB];
                split_pack(c0, c1, BBhi[ks][r], BBlo[ks][r]);
            }
        }
        __syncthreads();   // XF ready for all warps

        // ---- mainloop over 8 M-tiles ----
        float* myPart = part + w * 256;
        #pragma unroll
        for (int m = 0; m < 8; m++) {
            uint2 A[2][4];
            #pragma unroll
            for (int ks = 0; ks < 2; ks++)
                #pragma unroll
                for (int r = 0; r < 4; r++)
                    A[ks][r] = XF[((m * 2 + ks) * 4 + r) * 32 + lane];

            float Ca[4] = {0.f, 0.f, 0.f, 0.f};
            float Cb[4] = {0.f, 0.f, 0.f, 0.f};
            #pragma unroll
            for (int ks = 0; ks < 2; ks++) {
                const uint32_t ah0 = A[ks][0].x, ah1 = A[ks][1].x, ah2 = A[ks][2].x, ah3 = A[ks][3].x;
                const uint32_t al0 = A[ks][0].y, al1 = A[ks][1].y, al2 = A[ks][2].y, al3 = A[ks][3].y;
                mma_bf16(Ca, ah0, ah1, ah2, ah3, BAhi[ks][0], BAhi[ks][1]);
                mma_bf16(Ca, ah0, ah1, ah2, ah3, BAlo[ks][0], BAlo[ks][1]);
                mma_bf16(Ca, al0, al1, al2, al3, BAhi[ks][0], BAhi[ks][1]);
                mma_bf16(Cb, ah0, ah1, ah2, ah3, BBhi[ks][0], BBhi[ks][1]);
                mma_bf16(Cb, ah0, ah1, ah2, ah3, BBlo[ks][0], BBlo[ks][1]);
                mma_bf16(Cb, al0, al1, al2, al3, BBhi[ks][0], BBhi[ks][1]);
            }

            Ca[0] += ba.x; Ca[1] += ba.y; Ca[2] += ba.x; Ca[3] += ba.y;
            Cb[0] += bb.x; Cb[1] += bb.y; Cb[2] += bb.x; Cb[3] += bb.y;
            const float g0 = Ca[0] * sigmoidf_fast(Cb[0]);
            const float g1 = Ca[1] * sigmoidf_fast(Cb[1]);
            const float g2 = Ca[2] * sigmoidf_fast(Cb[2]);
            const float g3 = Ca[3] * sigmoidf_fast(Cb[3]);
            float accLo0 = g0 * w2f.x + g1 * w2f.z;
            float accLo1 = g0 * w2f.y + g1 * w2f.w;
            float accHi0 = g2 * w2f.x + g3 * w2f.z;
            float accHi1 = g2 * w2f.y + g3 * w2f.w;

            accLo0 += __shfl_xor_sync(0xffffffffu, accLo0, 1);
            accLo0 += __shfl_xor_sync(0xffffffffu, accLo0, 2);
            accLo1 += __shfl_xor_sync(0xffffffffu, accLo1, 1);
            accLo1 += __shfl_xor_sync(0xffffffffu, accLo1, 2);
            accHi0 += __shfl_xor_sync(0xffffffffu, accHi0, 1);
            accHi0 += __shfl_xor_sync(0xffffffffu, accHi0, 2);
            accHi1 += __shfl_xor_sync(0xffffffffu, accHi1, 1);
            accHi1 += __shfl_xor_sync(0xffffffffu, accHi1, 2);
            if (q == 0) {
                const int r0 = m * 16 + lr;
                myPart[r0 * 2 + 0]       = accLo0;
                myPart[r0 * 2 + 1]       = accLo1;
                myPart[(r0 + 8) * 2 + 0] = accHi0;
                myPart[(r0 + 8) * 2 + 1] = accHi1;
            }
        }
        __syncthreads();   // partials ready

        // ---- final: sum 16 warp partials, GLU2, /T, store ----
        if (tid < 128) {
            float y0 = b2v.x;
            float y1 = b2v.y;
            #pragma unroll
            for (int ww = 0; ww < 16; ww++) {
                const float2 pv = *reinterpret_cast<const float2*>(&part[ww * 256 + tid * 2]);
                y0 += pv.x;
                y1 += pv.y;
            }
            out[(size_t)tid * NN + n] = (y0 * sigmoidf_fast(y1)) / Tval;
        }
        // no trailing sync needed: next iteration starts with cp_wait0 + __syncthreads
    }
}

extern "C" void kernel_launch(void* const* d_in, const int* in_sizes, int n_in,
                              void* d_out, int out_size) {
    const float* state = (const float*)d_in[0];
    const float* w1    = (const float*)d_in[1];
    const float* b1    = (const float*)d_in[2];
    const float* w2    = (const float*)d_in[3];
    const float* b2    = (const float*)d_in[4];
    const float* T     = (const float*)d_in[5];
    float* out = (float*)d_out;
    cudaFuncSetAttribute(nlm_kernel, cudaFuncAttributeMaxDynamicSharedMemorySize, SMEM_TOTAL);
    nlm_kernel<<<GRID, 512, SMEM_TOTAL>>>(state, w1, b1, w2, b2, T, out);
}

// round 4
// speedup vs baseline: 1.8509x; 1.8509x over previous
#include <cuda_runtime.h>
#include <cuda_fp16.h>
#include <cstdint>

#define NN        2048
#define MEM       32
#define HID       256
#define W1S_STRIDE 260   // words; 1040B row (16B multiple), conflict-free fragment gathers

// dynamic smem layout (bytes)
#define OFF_W1S   0
#define SZ_W1S    (32 * W1S_STRIDE * 4)          // 33280
#define OFF_XF    SZ_W1S                         // 33280
#define SZ_XF     (2048 * 4)                     // 8192 (fp16x2 hi only)
#define OFF_PART  (OFF_XF + SZ_XF)               // 41472
#define SMEM_TOTAL (OFF_PART + 8192)             // 49664

__device__ __forceinline__ float sigmoidf_fast(float x) {
    return __fdividef(1.0f, 1.0f + __expf(-x));
}

__device__ __forceinline__ void mma_f16(float c[4],
                                        uint32_t a0, uint32_t a1, uint32_t a2, uint32_t a3,
                                        uint32_t b0, uint32_t b1) {
    asm volatile(
        "mma.sync.aligned.m16n8k16.row.col.f32.f16.f16.f32 "
        "{%0,%1,%2,%3}, {%4,%5,%6,%7}, {%8,%9}, {%0,%1,%2,%3};"
        : "+f"(c[0]), "+f"(c[1]), "+f"(c[2]), "+f"(c[3])
        : "r"(a0), "r"(a1), "r"(a2), "r"(a3), "r"(b0), "r"(b1));
}

// Split two f32 into fp16 hi/lo packed pairs (x low half, y high half).
__device__ __forceinline__ void split_pack16(float x, float y, uint32_t& hi, uint32_t& lo) {
    half2 h = __floats2half2_rn(x, y);
    float2 hf = __half22float2(h);
    half2 l = __floats2half2_rn(x - hf.x, y - hf.y);
    hi = *reinterpret_cast<uint32_t*>(&h);
    lo = *reinterpret_cast<uint32_t*>(&l);
}

__device__ __forceinline__ void cp16(uint32_t dst, const void* src) {
    asm volatile("cp.async.cg.shared.global [%0], [%1], 16;" :: "r"(dst), "l"(src));
}

__global__ __launch_bounds__(256, 3)
void nlm_kernel(const float* __restrict__ state,   // (128, 2048, 32)
                const float* __restrict__ w1,      // (2048, 32, 256)
                const float* __restrict__ b1,      // (2048, 256)
                const float* __restrict__ w2,      // (2048, 128, 2)
                const float* __restrict__ b2,      // (2048, 2)
                const float* __restrict__ Tg,      // (1,)
                float* __restrict__ out)           // (128, 2048)
{
    extern __shared__ char smem[];
    const uint32_t sbase = (uint32_t)__cvta_generic_to_shared(smem);
    float*    W1s  = (float*)(smem + OFF_W1S);
    uint32_t* XF   = (uint32_t*)(smem + OFF_XF);
    float*    part = (float*)(smem + OFF_PART);

    const int n    = blockIdx.x;
    const int tid  = threadIdx.x;
    const int w    = tid >> 5;     // warp 0..7, owns GLU column-pair tiles {2w, 2w+1}
    const int lane = tid & 31;
    const int q    = lane & 3;
    const int lr   = lane >> 2;

    // ---------------- Prologue ----------------
    const float* W1g = w1 + (size_t)n * (MEM * HID);
    // W1 -> padded smem via cp.async (8 x 16B per thread, fully coalesced)
    #pragma unroll
    for (int i = 0; i < 8; i++) {
        const int t  = tid + i * 256;
        const int c4 = t & 63;
        const int k  = t >> 6;
        cp16(sbase + OFF_W1S + (k * W1S_STRIDE + 4 * c4) * 4, W1g + k * HID + 4 * c4);
    }
    asm volatile("cp.async.commit_group;");

    // X: 4 x LDG.128 per thread -> fp16 hi fragments -> STS.64
    const float* Xg = state + (size_t)n * MEM;
    #pragma unroll
    for (int i = 0; i < 4; i++) {
        const int t    = tid + i * 256;
        const int s    = t & 7;          // float4 index in row (k0 = 4s)
        const int brow = t >> 3;         // batch row
        const float4 v = *reinterpret_cast<const float4*>(Xg + (size_t)brow * (NN * MEM) + 4 * s);
        const int p0   = 2 * s;
        const int q0   = p0 & 3;
        const int reg2 = (p0 >> 2) & 1;
        const int ks   = p0 >> 3;
        const int flr  = brow & 7;
        const int reg  = ((brow >> 3) & 1) + 2 * reg2;
        const int m    = brow >> 4;
        const int idx  = ((m * 2 + ks) * 4 + reg) * 32 + flr * 4 + q0;
        half2 ha = __floats2half2_rn(v.x, v.y);
        half2 hb = __floats2half2_rn(v.z, v.w);
        uint2 st;
        st.x = *reinterpret_cast<uint32_t*>(&ha);
        st.y = *reinterpret_cast<uint32_t*>(&hb);
        *reinterpret_cast<uint2*>(&XF[idx]) = st;
    }

    // per-warp bias / W2 registers
    const int h0 = (2 * w) * 8 + 2 * q;                 // first tile's g-col (even)
    const float2 ba0 = *reinterpret_cast<const float2*>(&b1[n * 256 + h0]);
    const float2 bb0 = *reinterpret_cast<const float2*>(&b1[n * 256 + 128 + h0]);
    const float2 ba1 = *reinterpret_cast<const float2*>(&b1[n * 256 + h0 + 8]);
    const float2 bb1 = *reinterpret_cast<const float2*>(&b1[n * 256 + 136 + h0]);
    const float4 w2f0 = *reinterpret_cast<const float4*>(&w2[n * 256 + h0 * 2]);
    const float4 w2f1 = *reinterpret_cast<const float4*>(&w2[n * 256 + (h0 + 8) * 2]);
    float2 b2v = make_float2(0.f, 0.f);
    if (tid < 128) b2v = *reinterpret_cast<const float2*>(&b2[n * 2]);
    const float Tval = Tg[0];

    asm volatile("cp.async.wait_group 0;");
    __syncthreads();

    // ---------------- Build W1 fp16 hi/lo fragments (conflict-free gathers) ----------------
    uint32_t BAhi[2][2][2], BAlo[2][2][2], BBhi[2][2][2], BBlo[2][2][2];
    #pragma unroll
    for (int p = 0; p < 2; p++) {
        const int colA = (2 * w + p) * 8 + lr;
        const int colB = colA + 128;
        #pragma unroll
        for (int ks = 0; ks < 2; ks++) {
            #pragma unroll
            for (int r = 0; r < 2; r++) {
                const int k = ks * 16 + r * 8 + 2 * q;
                split_pack16(W1s[k * W1S_STRIDE + colA], W1s[(k + 1) * W1S_STRIDE + colA],
                             BAhi[p][ks][r], BAlo[p][ks][r]);
                split_pack16(W1s[k * W1S_STRIDE + colB], W1s[(k + 1) * W1S_STRIDE + colB],
                             BBhi[p][ks][r], BBlo[p][ks][r]);
            }
        }
    }

    // ---------------- Mainloop ----------------
    float* myPart = part + w * 256;
    #pragma unroll
    for (int m = 0; m < 8; m++) {
        uint32_t A[2][4];
        #pragma unroll
        for (int ks = 0; ks < 2; ks++)
            #pragma unroll
            for (int r = 0; r < 4; r++)
                A[ks][r] = XF[((m * 2 + ks) * 4 + r) * 32 + lane];

        float accLo0 = 0.f, accLo1 = 0.f, accHi0 = 0.f, accHi1 = 0.f;

        #pragma unroll
        for (int p = 0; p < 2; p++) {
            const float2 ba = p ? ba1 : ba0;
            const float2 bb = p ? bb1 : bb0;
            const float4 w2f = p ? w2f1 : w2f0;
            float Ca[4] = {ba.x, ba.y, ba.x, ba.y};   // bias folded into C init
            float Cb[4] = {bb.x, bb.y, bb.x, bb.y};
            #pragma unroll
            for (int ks = 0; ks < 2; ks++) {
                // 2-term fp16: Ah*Bh + Ah*Bl  (A residual dropped: err ~2^-11)
                mma_f16(Ca, A[ks][0], A[ks][1], A[ks][2], A[ks][3], BAhi[p][ks][0], BAhi[p][ks][1]);
                mma_f16(Ca, A[ks][0], A[ks][1], A[ks][2], A[ks][3], BAlo[p][ks][0], BAlo[p][ks][1]);
                mma_f16(Cb, A[ks][0], A[ks][1], A[ks][2], A[ks][3], BBhi[p][ks][0], BBhi[p][ks][1]);
                mma_f16(Cb, A[ks][0], A[ks][1], A[ks][2], A[ks][3], BBlo[p][ks][0], BBlo[p][ks][1]);
            }
            const float g0 = Ca[0] * sigmoidf_fast(Cb[0]);
            const float g1 = Ca[1] * sigmoidf_fast(Cb[1]);
            const float g2 = Ca[2] * sigmoidf_fast(Cb[2]);
            const float g3 = Ca[3] * sigmoidf_fast(Cb[3]);
            accLo0 += g0 * w2f.x + g1 * w2f.z;
            accLo1 += g0 * w2f.y + g1 * w2f.w;
            accHi0 += g2 * w2f.x + g3 * w2f.z;
            accHi1 += g2 * w2f.y + g3 * w2f.w;
        }

        accLo0 += __shfl_xor_sync(0xffffffffu, accLo0, 1);
        accLo0 += __shfl_xor_sync(0xffffffffu, accLo0, 2);
        accLo1 += __shfl_xor_sync(0xffffffffu, accLo1, 1);
        accLo1 += __shfl_xor_sync(0xffffffffu, accLo1, 2);
        accHi0 += __shfl_xor_sync(0xffffffffu, accHi0, 1);
        accHi0 += __shfl_xor_sync(0xffffffffu, accHi0, 2);
        accHi1 += __shfl_xor_sync(0xffffffffu, accHi1, 1);
        accHi1 += __shfl_xor_sync(0xffffffffu, accHi1, 2);
        if (q == 0) {
            const int r0 = m * 16 + lr;
            myPart[r0 * 2 + 0]       = accLo0;
            myPart[r0 * 2 + 1]       = accLo1;
            myPart[(r0 + 8) * 2 + 0] = accHi0;
            myPart[(r0 + 8) * 2 + 1] = accHi1;
        }
    }

    __syncthreads();

    // ---------------- Final: sum 8 warp partials, GLU2, /T, store ----------------
    if (tid < 128) {
        float y0 = b2v.x;
        float y1 = b2v.y;
        #pragma unroll
        for (int ww = 0; ww < 8; ww++) {
            const float2 pv = *reinterpret_cast<const float2*>(&part[ww * 256 + tid * 2]);
            y0 += pv.x;
            y1 += pv.y;
        }
        out[(size_t)tid * NN + n] = (y0 * sigmoidf_fast(y1)) / Tval;
    }
}

extern "C" void kernel_launch(void* const* d_in, const int* in_sizes, int n_in,
                              void* d_out, int out_size) {
    const float* state = (const float*)d_in[0];
    const float* w1    = (const float*)d_in[1];
    const float* b1    = (const float*)d_in[2];
    const float* w2    = (const float*)d_in[3];
    const float* b2    = (const float*)d_in[4];
    const float* T     = (const float*)d_in[5];
    float* out = (float*)d_out;
    cudaFuncSetAttribute(nlm_kernel, cudaFuncAttributeMaxDynamicSharedMemorySize, SMEM_TOTAL);
    nlm_kernel<<<NN, 256, SMEM_TOTAL>>>(state, w1, b1, w2, b2, T, out);
}